// round 1
// baseline (speedup 1.0000x reference)
#include <cuda_runtime.h>
#include <math.h>

#define EPSV 1e-20f

// Problem dims (fixed by the dataset)
#define BB 16
#define H0 352
#define W0 1216
#define H1 176
#define W1 608
#define H2 88
#define W2 304
#define H3 44
#define W3 152

#define P0 (H0*W0)   // 428032
#define P1 (H1*W1)   // 107008
#define P2 (H2*W2)   // 26752
#define P3 (H3*W3)   // 6688

// Scratch sizes (floats), 2-channel tensors
#define N0 ((size_t)BB*2*P0)  // 13,697,024
#define N1 ((size_t)BB*2*P1)  // 3,424,256
#define N2 ((size_t)BB*2*P2)  // 856,064
#define N3 ((size_t)BB*2*P3)  // 214,016

// total = 6*N0 + 6*N1 + 6*N2 + 4*N3 = 108,720,128 floats (~435 MB)
__device__ float g_scratch[6*N0 + 6*N1 + 6*N2 + 4*N3];
__device__ float g_w[512];   // softplus'd weights + per-out-channel sums

// weight offsets inside g_w
// w1:0(50) w2:50(100) w3:150(100) w4:250(72) w5:322(72) w6:394(72) w7:466(2)
// sums: s1:468 s2:470 s3:472 s4:474 s5:476 s6:478 s7:480

__device__ __forceinline__ float sp10(float p){
    float z = 10.0f * p;
    float r = (z > 20.0f) ? z : log1pf(expf(z));
    return r * 0.1f;
}

__global__ void k_prep(const float* __restrict__ w1, const float* __restrict__ w2,
                       const float* __restrict__ w3, const float* __restrict__ w4,
                       const float* __restrict__ w5, const float* __restrict__ w6,
                       const float* __restrict__ w7){
    const float* src[7] = {w1,w2,w3,w4,w5,w6,w7};
    const int   cnt[7]  = {50,100,100,72,72,72,2};
    const int   off[7]  = {0,50,150,250,322,394,466};
    int t = threadIdx.x;
    for(int a=0;a<7;a++){
        for(int i=t;i<cnt[a];i+=blockDim.x)
            g_w[off[a]+i] = sp10(src[a][i]);
    }
    __syncthreads();
    if(t==0){
        const int ncout[7] = {2,2,2,2,2,2,1};
        const int per[7]   = {25,50,50,36,36,36,2};
        const int soff[7]  = {468,470,472,474,476,478,480};
        for(int a=0;a<7;a++){
            for(int co=0;co<ncout[a];co++){
                float s=0.f;
                for(int i=0;i<per[a];i++) s += g_w[off[a]+co*per[a]+i];
                g_w[soff[a]+co]=s;
            }
        }
    }
}

// 5x5 normalized conv, COUT=2, pad=2. One thread = one output pixel (all couts).
template<int CIN>
__global__ void k_nconv5(const float* __restrict__ xin, const float* __restrict__ cin,
                         const float* __restrict__ w,  const float* __restrict__ wsum,
                         const float* __restrict__ bias,
                         float* __restrict__ xout, float* __restrict__ cout_,
                         int H, int W){
    __shared__ float wsm[2*CIN*25+2];
    for(int i=threadIdx.x;i<2*CIN*25;i+=blockDim.x) wsm[i]=w[i];
    if(threadIdx.x<2) wsm[2*CIN*25+threadIdx.x]=wsum[threadIdx.x];
    __syncthreads();

    int idx = blockIdx.x*blockDim.x + threadIdx.x;
    int P = H*W;
    if(idx >= BB*P) return;
    int x = idx % W;
    int y = (idx / W) % H;
    int b = idx / P;

    float den0=0.f, nom0=0.f, den1=0.f, nom1=0.f;
    #pragma unroll
    for(int ci=0;ci<CIN;ci++){
        const float* cb = cin + (size_t)(b*CIN+ci)*P;
        const float* xb = xin + (size_t)(b*CIN+ci)*P;
        #pragma unroll
        for(int ky=0;ky<5;ky++){
            int iy = y + ky - 2;
            if((unsigned)iy >= (unsigned)H) continue;
            #pragma unroll
            for(int kx=0;kx<5;kx++){
                int ix = x + kx - 2;
                if((unsigned)ix >= (unsigned)W) continue;
                int o = iy*W + ix;
                float c = cb[o];
                float d = xb[o]*c;
                float a0 = wsm[ci*25 + ky*5 + kx];
                float a1 = wsm[CIN*25 + ci*25 + ky*5 + kx];
                den0 += a0*c; nom0 += a0*d;
                den1 += a1*c; nom1 += a1*d;
            }
        }
    }
    size_t o0 = (size_t)(b*2+0)*P + (size_t)y*W + x;
    size_t o1 = (size_t)(b*2+1)*P + (size_t)y*W + x;
    xout[o0] = nom0/(den0+EPSV) + bias[0];
    xout[o1] = nom1/(den1+EPSV) + bias[1];
    cout_[o0] = den0/wsm[2*CIN*25];
    cout_[o1] = den1/wsm[2*CIN*25+1];
}

// 3x3 normalized conv on channel-concat of (native 2ch, nearest-upsampled-2x 2ch).
// UP_FIRST=true  : channels 0-1 = upsampled tensor (xb,cb at H/2 x W/2), 2-3 = native (xa,ca)
// UP_FIRST=false : channels 0-1 = native, 2-3 = upsampled
template<bool UP_FIRST>
__global__ void k_nconv3_cat(const float* __restrict__ xa, const float* __restrict__ ca,
                             const float* __restrict__ xb, const float* __restrict__ cb,
                             const float* __restrict__ w,  const float* __restrict__ wsum,
                             const float* __restrict__ bias,
                             float* __restrict__ xout, float* __restrict__ cout_,
                             int H, int W){
    __shared__ float wsm[2*4*9+2];
    for(int i=threadIdx.x;i<2*4*9;i+=blockDim.x) wsm[i]=w[i];
    if(threadIdx.x<2) wsm[72+threadIdx.x]=wsum[threadIdx.x];
    __syncthreads();

    int idx = blockIdx.x*blockDim.x + threadIdx.x;
    int P = H*W;
    if(idx >= BB*P) return;
    int x = idx % W;
    int y = (idx / W) % H;
    int b = idx / P;
    int Wh = W>>1, Hh = H>>1;
    int Ph = Wh*Hh;

    float den0=0.f, nom0=0.f, den1=0.f, nom1=0.f;
    #pragma unroll
    for(int ci=0;ci<4;ci++){
        const bool fromUp = UP_FIRST ? (ci<2) : (ci>=2);
        const int ch = fromUp ? (UP_FIRST ? ci : ci-2) : (UP_FIRST ? ci-2 : ci);
        const float* cs = fromUp ? (cb + (size_t)(b*2+ch)*Ph) : (ca + (size_t)(b*2+ch)*P);
        const float* xs = fromUp ? (xb + (size_t)(b*2+ch)*Ph) : (xa + (size_t)(b*2+ch)*P);
        #pragma unroll
        for(int ky=0;ky<3;ky++){
            int iy = y + ky - 1;
            if((unsigned)iy >= (unsigned)H) continue;
            #pragma unroll
            for(int kx=0;kx<3;kx++){
                int ix = x + kx - 1;
                if((unsigned)ix >= (unsigned)W) continue;
                float c, d;
                if(fromUp){
                    int o = (iy>>1)*Wh + (ix>>1);
                    c = cs[o]; d = xs[o]*c;
                } else {
                    int o = iy*W + ix;
                    c = cs[o]; d = xs[o]*c;
                }
                float a0 = wsm[ci*9 + ky*3 + kx];
                float a1 = wsm[36 + ci*9 + ky*3 + kx];
                den0 += a0*c; nom0 += a0*d;
                den1 += a1*c; nom1 += a1*d;
            }
        }
    }
    size_t o0 = (size_t)(b*2+0)*P + (size_t)y*W + x;
    size_t o1 = (size_t)(b*2+1)*P + (size_t)y*W + x;
    xout[o0] = nom0/(den0+EPSV) + bias[0];
    xout[o1] = nom1/(den1+EPSV) + bias[1];
    cout_[o0] = den0/wsm[72];
    cout_[o1] = den1/wsm[73];
}

// 2x2 max-pool on conf (first-max, row-major window order), gather x at argmax.
// cds = max/4. Input planes are (2Hh x 2Wh), BB*2 planes total.
__global__ void k_pool(const float* __restrict__ cin, const float* __restrict__ xin,
                       float* __restrict__ cds, float* __restrict__ xds,
                       int Hh, int Wh){
    int idx = blockIdx.x*blockDim.x + threadIdx.x;
    int total = BB*2*Hh*Wh;
    if(idx >= total) return;
    int x = idx % Wh;
    int y = (idx / Wh) % Hh;
    int pl = idx / (Hh*Wh);
    int Wi = Wh*2;
    size_t base = (size_t)pl*(Hh*2)*Wi + (size_t)(2*y)*Wi + 2*x;
    float c00=cin[base],    c01=cin[base+1];
    float c10=cin[base+Wi], c11=cin[base+Wi+1];
    float x00=xin[base],    x01=xin[base+1];
    float x10=xin[base+Wi], x11=xin[base+Wi+1];
    float best=c00, bx=x00;
    if(c01>best){best=c01;bx=x01;}
    if(c10>best){best=c10;bx=x10;}
    if(c11>best){best=c11;bx=x11;}
    cds[idx]=best*0.25f;
    xds[idx]=bx;
}

// final 1x1 nconv: 2ch -> 1ch, writes xout then cout contiguously into d_out
__global__ void k_nconv1x1(const float* __restrict__ xin, const float* __restrict__ cin,
                           const float* __restrict__ w, const float* __restrict__ wsum,
                           const float* __restrict__ bias,
                           float* __restrict__ xout, float* __restrict__ cout_){
    int idx = blockIdx.x*blockDim.x + threadIdx.x;
    if(idx >= BB*P0) return;
    int pix = idx % P0;
    int b = idx / P0;
    size_t o0 = (size_t)(b*2+0)*P0 + pix;
    size_t o1 = (size_t)(b*2+1)*P0 + pix;
    float c0v = cin[o0], c1v = cin[o1];
    float d0 = xin[o0]*c0v, d1 = xin[o1]*c1v;
    float w0 = w[0], w1 = w[1];
    float den = w0*c0v + w1*c1v;
    float nom = w0*d0 + w1*d1;
    xout[idx]  = nom/(den+EPSV) + bias[0];
    cout_[idx] = den/wsum[0];
}

extern "C" void kernel_launch(void* const* d_in, const int* in_sizes, int n_in,
                              void* d_out, int out_size){
    const float* x0 = (const float*)d_in[0];
    const float* c0 = (const float*)d_in[1];
    const float* w1 = (const float*)d_in[2];  const float* b1 = (const float*)d_in[3];
    const float* w2 = (const float*)d_in[4];  const float* b2 = (const float*)d_in[5];
    const float* w3 = (const float*)d_in[6];  const float* b3 = (const float*)d_in[7];
    const float* w4 = (const float*)d_in[8];  const float* b4 = (const float*)d_in[9];
    const float* w5 = (const float*)d_in[10]; const float* b5 = (const float*)d_in[11];
    const float* w6 = (const float*)d_in[12]; const float* b6 = (const float*)d_in[13];
    const float* w7 = (const float*)d_in[14]; const float* b7 = (const float*)d_in[15];

    float* S = nullptr;  cudaGetSymbolAddress((void**)&S,  g_scratch);
    float* Wt = nullptr; cudaGetSymbolAddress((void**)&Wt, g_w);

    // carve scratch
    float *xA=S,        *cA=S+N0,     *xB=S+2*N0, *cB=S+3*N0, *x1=S+4*N0, *c1=S+5*N0;
    float *Sh = S + 6*N0;
    float *xha=Sh,      *cha=Sh+N1,   *xhb=Sh+2*N1, *chb=Sh+3*N1, *x2d=Sh+4*N1, *c2d=Sh+5*N1;
    float *Sq = Sh + 6*N1;
    float *xq=Sq,       *cq=Sq+N2,    *x3d=Sq+2*N2, *c3d=Sq+3*N2, *x34=Sq+4*N2, *c34=Sq+5*N2;
    float *Se = Sq + 6*N2;
    float *xe=Se,       *ce=Se+N3,    *x4=Se+2*N3,  *c4=Se+3*N3;

    const int thr = 256;
    auto gb = [&](long n){ return (int)((n + thr - 1) / thr); };

    k_prep<<<1,128>>>(w1,w2,w3,w4,w5,w6,w7);

    // encoder, full res
    k_nconv5<1><<<gb((long)BB*P0),thr>>>(x0, c0, Wt+0,   Wt+468, b1, xA, cA, H0, W0);
    k_nconv5<2><<<gb((long)BB*P0),thr>>>(xA, cA, Wt+50,  Wt+470, b2, xB, cB, H0, W0);
    k_nconv5<2><<<gb((long)BB*P0),thr>>>(xB, cB, Wt+150, Wt+472, b3, x1, c1, H0, W0);

    // level 1
    k_pool<<<gb((long)BB*2*P1),thr>>>(c1, x1, cha, xha, H1, W1);
    k_nconv5<2><<<gb((long)BB*P1),thr>>>(xha, cha, Wt+50,  Wt+470, b2, xhb, chb, H1, W1);
    k_nconv5<2><<<gb((long)BB*P1),thr>>>(xhb, chb, Wt+150, Wt+472, b3, x2d, c2d, H1, W1);

    // level 2
    k_pool<<<gb((long)BB*2*P2),thr>>>(c2d, x2d, cq, xq, H2, W2);
    k_nconv5<2><<<gb((long)BB*P2),thr>>>(xq, cq, Wt+50, Wt+470, b2, x3d, c3d, H2, W2);

    // level 3
    k_pool<<<gb((long)BB*2*P3),thr>>>(c3d, x3d, ce, xe, H3, W3);
    k_nconv5<2><<<gb((long)BB*P3),thr>>>(xe, ce, Wt+50, Wt+470, b2, x4, c4, H3, W3);

    // decoder (concat with fused nearest-2x upsample of the second tensor)
    // nconv4: concat(x3_ds, up(x4))  -> native first
    k_nconv3_cat<false><<<gb((long)BB*P2),thr>>>(x3d, c3d, x4, c4,
                                                 Wt+250, Wt+474, b4, x34, c34, H2, W2);
    // nconv5: concat(x2_ds, up(x34)) -> native first  (reuse xha/cha as x23 storage)
    k_nconv3_cat<false><<<gb((long)BB*P1),thr>>>(x2d, c2d, x34, c34,
                                                 Wt+322, Wt+476, b5, xha, cha, H1, W1);
    // nconv6: concat(up(x23), x1)    -> upsampled first (reuse xA/cA)
    k_nconv3_cat<true><<<gb((long)BB*P0),thr>>>(x1, c1, xha, cha,
                                                Wt+394, Wt+478, b6, xA, cA, H0, W0);

    // final 1x1 nconv -> d_out = [xout | cout]
    float* out = (float*)d_out;
    k_nconv1x1<<<gb((long)BB*P0),thr>>>(xA, cA, Wt+466, Wt+480, b7,
                                        out, out + (size_t)BB*P0);
}

// round 2
// speedup vs baseline: 1.6805x; 1.6805x over previous
#include <cuda_runtime.h>
#include <math.h>

#define EPSV 1e-20f

#define BB 16
#define H0 352
#define W0 1216
#define H1 176
#define W1 608
#define H2 88
#define W2 304
#define H3 44
#define W3 152

#define P0 (H0*W0)
#define P1 (H1*W1)
#define P2 (H2*W2)
#define P3 (H3*W3)

#define N0 ((size_t)BB*2*P0)
#define N1 ((size_t)BB*2*P1)
#define N2 ((size_t)BB*2*P2)
#define N3 ((size_t)BB*2*P3)

__device__ float g_scratch[6*N0 + 6*N1 + 6*N2 + 4*N3];
__device__ float g_w[512];

// weight offsets: w1:0(50) w2:50(100) w3:150(100) w4:250(72) w5:322(72) w6:394(72) w7:466(2)
// sums: s1:468 s2:470 s3:472 s4:474 s5:476 s6:478 s7:480

__device__ __forceinline__ float sp10(float p){
    float z = 10.0f * p;
    float r = (z > 20.0f) ? z : log1pf(expf(z));
    return r * 0.1f;
}

__global__ void k_prep(const float* __restrict__ w1, const float* __restrict__ w2,
                       const float* __restrict__ w3, const float* __restrict__ w4,
                       const float* __restrict__ w5, const float* __restrict__ w6,
                       const float* __restrict__ w7){
    const float* src[7] = {w1,w2,w3,w4,w5,w6,w7};
    const int   cnt[7]  = {50,100,100,72,72,72,2};
    const int   off[7]  = {0,50,150,250,322,394,466};
    int t = threadIdx.x;
    for(int a=0;a<7;a++){
        for(int i=t;i<cnt[a];i+=blockDim.x)
            g_w[off[a]+i] = sp10(src[a][i]);
    }
    __syncthreads();
    if(t==0){
        const int ncout[7] = {2,2,2,2,2,2,1};
        const int per[7]   = {25,50,50,36,36,36,2};
        const int soff[7]  = {468,470,472,474,476,478,480};
        for(int a=0;a<7;a++){
            for(int co=0;co<ncout[a];co++){
                float s=0.f;
                for(int i=0;i<per[a];i++) s += g_w[off[a]+co*per[a]+i];
                g_w[soff[a]+co]=s;
            }
        }
    }
}

// ---------------- tiled 5x5 normalized conv, COUT=2, pad=2 ----------------
// Block = 256 threads, computes a 64x16 output tile; each thread a 2x2 quad.
#define TX5 64
#define TY5 16
#define SW5 (TX5+4)   // 68
#define SH5 (TY5+4)   // 20

template<int CIN>
__global__ void __launch_bounds__(256)
k_nconv5t(const float* __restrict__ xin, const float* __restrict__ cin,
          const float* __restrict__ w,  const float* __restrict__ wsum,
          const float* __restrict__ bias,
          float* __restrict__ xout, float* __restrict__ cout_,
          int H, int W, int bpr, int bpc){
    __shared__ float smc[CIN][SH5*SW5];
    __shared__ float smd[CIN][SH5*SW5];
    __shared__ float wsm[2*CIN*25+4];

    const int t = threadIdx.x;
    const int P = H*W;

    for(int i=t;i<2*CIN*25;i+=256) wsm[i]=w[i];
    if(t<2){ wsm[2*CIN*25+t]=wsum[t]; wsm[2*CIN*25+2+t]=bias[t]; }

    int bx = blockIdx.x % bpr;
    int tmp = blockIdx.x / bpr;
    int by = tmp % bpc;
    int b  = tmp / bpc;
    int gx0 = bx*TX5 - 2;
    int gy0 = by*TY5 - 2;

    #pragma unroll
    for(int ci=0;ci<CIN;ci++){
        const float* cb = cin + (size_t)(b*CIN+ci)*P;
        const float* xb = xin + (size_t)(b*CIN+ci)*P;
        for(int i=t;i<SH5*SW5;i+=256){
            int lx = i % SW5, ly = i / SW5;
            int gx = gx0+lx, gy = gy0+ly;
            float c=0.f, d=0.f;
            if((unsigned)gx<(unsigned)W && (unsigned)gy<(unsigned)H){
                int o = gy*W+gx;
                c = cb[o]; d = xb[o]*c;
            }
            smc[ci][i]=c; smd[ci][i]=d;
        }
    }
    __syncthreads();

    const int tx = (t & 31)*2;
    const int ty = (t >> 5)*2;

    float dn[2][2][2], nm[2][2][2];
    #pragma unroll
    for(int a=0;a<2;a++)
      #pragma unroll
      for(int dy=0;dy<2;dy++)
        #pragma unroll
        for(int dx=0;dx<2;dx++){ dn[a][dy][dx]=0.f; nm[a][dy][dx]=0.f; }

    #pragma unroll
    for(int ci=0;ci<CIN;ci++){
        const float* wc0 = &wsm[ci*25];
        const float* wc1 = &wsm[CIN*25+ci*25];
        #pragma unroll
        for(int r=0;r<6;r++){
            int base = (ty+r)*SW5 + tx;   // even -> float2 aligned
            float cc[6], dd[6];
            const float2* pc = (const float2*)&smc[ci][base];
            const float2* pd = (const float2*)&smd[ci][base];
            #pragma unroll
            for(int j=0;j<3;j++){
                float2 v=pc[j]; cc[2*j]=v.x; cc[2*j+1]=v.y;
                float2 u=pd[j]; dd[2*j]=u.x; dd[2*j+1]=u.y;
            }
            #pragma unroll
            for(int dy=0;dy<2;dy++){
                int ky = r - dy;
                if(ky<0 || ky>4) continue;
                #pragma unroll
                for(int kx=0;kx<5;kx++){
                    float a0=wc0[ky*5+kx], a1=wc1[ky*5+kx];
                    #pragma unroll
                    for(int dx=0;dx<2;dx++){
                        dn[0][dy][dx] += a0*cc[kx+dx];
                        nm[0][dy][dx] += a0*dd[kx+dx];
                        dn[1][dy][dx] += a1*cc[kx+dx];
                        nm[1][dy][dx] += a1*dd[kx+dx];
                    }
                }
            }
        }
    }

    float rs0 = 1.0f/wsm[2*CIN*25];
    float rs1 = 1.0f/wsm[2*CIN*25+1];
    float bi0 = wsm[2*CIN*25+2];
    float bi1 = wsm[2*CIN*25+3];
    #pragma unroll
    for(int dy=0;dy<2;dy++){
        int gy = by*TY5 + ty + dy;
        if(gy>=H) continue;
        #pragma unroll
        for(int dx=0;dx<2;dx++){
            int gx = bx*TX5 + tx + dx;
            if(gx>=W) continue;
            size_t o0 = (size_t)(b*2+0)*P + (size_t)gy*W + gx;
            size_t o1 = (size_t)(b*2+1)*P + (size_t)gy*W + gx;
            xout[o0]  = nm[0][dy][dx]/(dn[0][dy][dx]+EPSV) + bi0;
            xout[o1]  = nm[1][dy][dx]/(dn[1][dy][dx]+EPSV) + bi1;
            cout_[o0] = dn[0][dy][dx]*rs0;
            cout_[o1] = dn[1][dy][dx]*rs1;
        }
    }
}

// ---------------- tiled 3x3 cat nconv (4 in-ch: 2 native + 2 upsampled) ----
#define TX3 64
#define TY3 16
#define SW3 (TX3+2)   // 66
#define SH3 (TY3+2)   // 18

template<bool UP_FIRST>
__global__ void __launch_bounds__(256)
k_nconv3t(const float* __restrict__ xa, const float* __restrict__ ca,
          const float* __restrict__ xb, const float* __restrict__ cb,
          const float* __restrict__ w,  const float* __restrict__ wsum,
          const float* __restrict__ bias,
          float* __restrict__ xout, float* __restrict__ cout_,
          int H, int W, int bpr, int bpc){
    __shared__ float smc[4][SH3*SW3];
    __shared__ float smd[4][SH3*SW3];
    __shared__ float wsm[76];

    const int t = threadIdx.x;
    const int P = H*W;
    const int Wh = W>>1, Ph = (W>>1)*(H>>1);

    for(int i=t;i<72;i+=256) wsm[i]=w[i];
    if(t<2){ wsm[72+t]=wsum[t]; wsm[74+t]=bias[t]; }

    int bx = blockIdx.x % bpr;
    int tmp = blockIdx.x / bpr;
    int by = tmp % bpc;
    int b  = tmp / bpc;
    int gx0 = bx*TX3 - 1;
    int gy0 = by*TY3 - 1;

    #pragma unroll
    for(int ci=0;ci<4;ci++){
        const bool fromUp = UP_FIRST ? (ci<2) : (ci>=2);
        const int ch = fromUp ? (UP_FIRST ? ci : ci-2) : (UP_FIRST ? ci-2 : ci);
        const float* cs = fromUp ? (cb + (size_t)(b*2+ch)*Ph) : (ca + (size_t)(b*2+ch)*P);
        const float* xs = fromUp ? (xb + (size_t)(b*2+ch)*Ph) : (xa + (size_t)(b*2+ch)*P);
        for(int i=t;i<SH3*SW3;i+=256){
            int lx = i % SW3, ly = i / SW3;
            int gx = gx0+lx, gy = gy0+ly;
            float c=0.f, d=0.f;
            if((unsigned)gx<(unsigned)W && (unsigned)gy<(unsigned)H){
                int o = fromUp ? ((gy>>1)*Wh + (gx>>1)) : (gy*W+gx);
                c = cs[o]; d = xs[o]*c;
            }
            smc[ci][i]=c; smd[ci][i]=d;
        }
    }
    __syncthreads();

    const int tx = (t & 31)*2;
    const int ty = (t >> 5)*2;

    float dn[2][2][2], nm[2][2][2];
    #pragma unroll
    for(int a=0;a<2;a++)
      #pragma unroll
      for(int dy=0;dy<2;dy++)
        #pragma unroll
        for(int dx=0;dx<2;dx++){ dn[a][dy][dx]=0.f; nm[a][dy][dx]=0.f; }

    #pragma unroll
    for(int ci=0;ci<4;ci++){
        const float* wc0 = &wsm[ci*9];
        const float* wc1 = &wsm[36+ci*9];
        #pragma unroll
        for(int r=0;r<4;r++){
            int base = (ty+r)*SW3 + tx;
            float cc[4], dd[4];
            const float2* pc = (const float2*)&smc[ci][base];
            const float2* pd = (const float2*)&smd[ci][base];
            #pragma unroll
            for(int j=0;j<2;j++){
                float2 v=pc[j]; cc[2*j]=v.x; cc[2*j+1]=v.y;
                float2 u=pd[j]; dd[2*j]=u.x; dd[2*j+1]=u.y;
            }
            #pragma unroll
            for(int dy=0;dy<2;dy++){
                int ky = r - dy;
                if(ky<0 || ky>2) continue;
                #pragma unroll
                for(int kx=0;kx<3;kx++){
                    float a0=wc0[ky*3+kx], a1=wc1[ky*3+kx];
                    #pragma unroll
                    for(int dx=0;dx<2;dx++){
                        dn[0][dy][dx] += a0*cc[kx+dx];
                        nm[0][dy][dx] += a0*dd[kx+dx];
                        dn[1][dy][dx] += a1*cc[kx+dx];
                        nm[1][dy][dx] += a1*dd[kx+dx];
                    }
                }
            }
        }
    }

    float rs0 = 1.0f/wsm[72];
    float rs1 = 1.0f/wsm[73];
    float bi0 = wsm[74];
    float bi1 = wsm[75];
    #pragma unroll
    for(int dy=0;dy<2;dy++){
        int gy = by*TY3 + ty + dy;
        if(gy>=H) continue;
        #pragma unroll
        for(int dx=0;dx<2;dx++){
            int gx = bx*TX3 + tx + dx;
            if(gx>=W) continue;
            size_t o0 = (size_t)(b*2+0)*P + (size_t)gy*W + gx;
            size_t o1 = (size_t)(b*2+1)*P + (size_t)gy*W + gx;
            xout[o0]  = nm[0][dy][dx]/(dn[0][dy][dx]+EPSV) + bi0;
            xout[o1]  = nm[1][dy][dx]/(dn[1][dy][dx]+EPSV) + bi1;
            cout_[o0] = dn[0][dy][dx]*rs0;
            cout_[o1] = dn[1][dy][dx]*rs1;
        }
    }
}

// 2x2 max-pool on conf (first-max, row-major order), gather x at argmax.
__global__ void k_pool(const float* __restrict__ cin, const float* __restrict__ xin,
                       float* __restrict__ cds, float* __restrict__ xds,
                       int Hh, int Wh){
    int idx = blockIdx.x*blockDim.x + threadIdx.x;
    int total = BB*2*Hh*Wh;
    if(idx >= total) return;
    int x = idx % Wh;
    int y = (idx / Wh) % Hh;
    int pl = idx / (Hh*Wh);
    int Wi = Wh*2;
    size_t base = (size_t)pl*(Hh*2)*Wi + (size_t)(2*y)*Wi + 2*x;
    float2 ct = *(const float2*)(cin+base);
    float2 cbm= *(const float2*)(cin+base+Wi);
    float2 xt = *(const float2*)(xin+base);
    float2 xbm= *(const float2*)(xin+base+Wi);
    float best=ct.x, bx=xt.x;
    if(ct.y >best){best=ct.y; bx=xt.y;}
    if(cbm.x>best){best=cbm.x;bx=xbm.x;}
    if(cbm.y>best){best=cbm.y;bx=xbm.y;}
    cds[idx]=best*0.25f;
    xds[idx]=bx;
}

__global__ void k_nconv1x1(const float* __restrict__ xin, const float* __restrict__ cin,
                           const float* __restrict__ w, const float* __restrict__ wsum,
                           const float* __restrict__ bias,
                           float* __restrict__ xout, float* __restrict__ cout_){
    int idx = blockIdx.x*blockDim.x + threadIdx.x;
    if(idx >= BB*P0) return;
    int pix = idx % P0;
    int b = idx / P0;
    size_t o0 = (size_t)(b*2+0)*P0 + pix;
    size_t o1 = (size_t)(b*2+1)*P0 + pix;
    float c0v = cin[o0], c1v = cin[o1];
    float d0 = xin[o0]*c0v, d1 = xin[o1]*c1v;
    float w0 = w[0], w1 = w[1];
    float den = w0*c0v + w1*c1v;
    float nom = w0*d0 + w1*d1;
    xout[idx]  = nom/(den+EPSV) + bias[0];
    cout_[idx] = den/wsum[0];
}

extern "C" void kernel_launch(void* const* d_in, const int* in_sizes, int n_in,
                              void* d_out, int out_size){
    const float* x0 = (const float*)d_in[0];
    const float* c0 = (const float*)d_in[1];
    const float* w1 = (const float*)d_in[2];  const float* b1 = (const float*)d_in[3];
    const float* w2 = (const float*)d_in[4];  const float* b2 = (const float*)d_in[5];
    const float* w3 = (const float*)d_in[6];  const float* b3 = (const float*)d_in[7];
    const float* w4 = (const float*)d_in[8];  const float* b4 = (const float*)d_in[9];
    const float* w5 = (const float*)d_in[10]; const float* b5 = (const float*)d_in[11];
    const float* w6 = (const float*)d_in[12]; const float* b6 = (const float*)d_in[13];
    const float* w7 = (const float*)d_in[14]; const float* b7 = (const float*)d_in[15];

    float* S = nullptr;  cudaGetSymbolAddress((void**)&S,  g_scratch);
    float* Wt = nullptr; cudaGetSymbolAddress((void**)&Wt, g_w);

    float *xA=S,   *cA=S+N0,   *xB=S+2*N0, *cB=S+3*N0, *x1=S+4*N0, *c1=S+5*N0;
    float *Sh = S + 6*N0;
    float *xha=Sh, *cha=Sh+N1, *xhb=Sh+2*N1, *chb=Sh+3*N1, *x2d=Sh+4*N1, *c2d=Sh+5*N1;
    float *Sq = Sh + 6*N1;
    float *xq=Sq,  *cq=Sq+N2,  *x3d=Sq+2*N2, *c3d=Sq+3*N2, *x34=Sq+4*N2, *c34=Sq+5*N2;
    float *Se = Sq + 6*N2;
    float *xe=Se,  *ce=Se+N3,  *x4=Se+2*N3,  *c4=Se+3*N3;

    const int thr = 256;
    auto gb = [&](long n){ return (int)((n + thr - 1) / thr); };
    auto tiles = [&](int H, int W, int &bpr, int &bpc)->int{
        bpr = (W + TX5 - 1)/TX5; bpc = (H + TY5 - 1)/TY5;
        return bpr*bpc*BB;
    };

    k_prep<<<1,128>>>(w1,w2,w3,w4,w5,w6,w7);

    int bpr, bpc, g;

    // encoder full res
    g = tiles(H0,W0,bpr,bpc);
    k_nconv5t<1><<<g,thr>>>(x0, c0, Wt+0,   Wt+468, b1, xA, cA, H0, W0, bpr, bpc);
    k_nconv5t<2><<<g,thr>>>(xA, cA, Wt+50,  Wt+470, b2, xB, cB, H0, W0, bpr, bpc);
    k_nconv5t<2><<<g,thr>>>(xB, cB, Wt+150, Wt+472, b3, x1, c1, H0, W0, bpr, bpc);

    // level 1
    k_pool<<<gb((long)BB*2*P1),thr>>>(c1, x1, cha, xha, H1, W1);
    g = tiles(H1,W1,bpr,bpc);
    k_nconv5t<2><<<g,thr>>>(xha, cha, Wt+50,  Wt+470, b2, xhb, chb, H1, W1, bpr, bpc);
    k_nconv5t<2><<<g,thr>>>(xhb, chb, Wt+150, Wt+472, b3, x2d, c2d, H1, W1, bpr, bpc);

    // level 2
    k_pool<<<gb((long)BB*2*P2),thr>>>(c2d, x2d, cq, xq, H2, W2);
    g = tiles(H2,W2,bpr,bpc);
    k_nconv5t<2><<<g,thr>>>(xq, cq, Wt+50, Wt+470, b2, x3d, c3d, H2, W2, bpr, bpc);

    // level 3
    k_pool<<<gb((long)BB*2*P3),thr>>>(c3d, x3d, ce, xe, H3, W3);
    g = tiles(H3,W3,bpr,bpc);
    k_nconv5t<2><<<g,thr>>>(xe, ce, Wt+50, Wt+470, b2, x4, c4, H3, W3, bpr, bpc);

    // decoder (fused nearest-2x upsample of second tensor)
    g = tiles(H2,W2,bpr,bpc);
    k_nconv3t<false><<<g,thr>>>(x3d, c3d, x4, c4,  Wt+250, Wt+474, b4, x34, c34, H2, W2, bpr, bpc);
    g = tiles(H1,W1,bpr,bpc);
    k_nconv3t<false><<<g,thr>>>(x2d, c2d, x34, c34, Wt+322, Wt+476, b5, xha, cha, H1, W1, bpr, bpc);
    g = tiles(H0,W0,bpr,bpc);
    k_nconv3t<true><<<g,thr>>>(x1, c1, xha, cha,   Wt+394, Wt+478, b6, xA, cA, H0, W0, bpr, bpc);

    float* out = (float*)d_out;
    k_nconv1x1<<<gb((long)BB*P0),thr>>>(xA, cA, Wt+466, Wt+480, b7,
                                        out, out + (size_t)BB*P0);
}

// round 3
// speedup vs baseline: 1.7899x; 1.0651x over previous
#include <cuda_runtime.h>
#include <math.h>

#define EPSV 1e-20f

#define BB 16
#define H0 352
#define W0 1216
#define H1 176
#define W1 608
#define H2 88
#define W2 304
#define H3 44
#define W3 152

#define P0 (H0*W0)
#define P1 (H1*W1)
#define P2 (H2*W2)
#define P3 (H3*W3)

#define N0 ((size_t)BB*2*P0)
#define N1 ((size_t)BB*2*P1)
#define N2 ((size_t)BB*2*P2)
#define N3 ((size_t)BB*2*P3)

__device__ float g_scratch[6*N0 + 6*N1 + 6*N2 + 4*N3];
__device__ float g_w[512];

// weight offsets: w1:0(50) w2:50(100) w3:150(100) w4:250(72) w5:322(72) w6:394(72) w7:466(2)
// sums: s1:468 s2:470 s3:472 s4:474 s5:476 s6:478 s7:480

typedef unsigned long long ull;

__device__ __forceinline__ ull fma2(ull a, ull b, ull c){
    ull d; asm("fma.rn.f32x2 %0, %1, %2, %3;" : "=l"(d) : "l"(a), "l"(b), "l"(c)); return d;
}
__device__ __forceinline__ void unpack2(ull v, float &a, float &b){
    asm("mov.b64 {%0,%1}, %2;" : "=f"(a), "=f"(b) : "l"(v));
}

__device__ __forceinline__ float sp10(float p){
    float z = 10.0f * p;
    float r = (z > 20.0f) ? z : log1pf(expf(z));
    return r * 0.1f;
}

__global__ void k_prep(const float* __restrict__ w1, const float* __restrict__ w2,
                       const float* __restrict__ w3, const float* __restrict__ w4,
                       const float* __restrict__ w5, const float* __restrict__ w6,
                       const float* __restrict__ w7){
    const float* src[7] = {w1,w2,w3,w4,w5,w6,w7};
    const int   cnt[7]  = {50,100,100,72,72,72,2};
    const int   off[7]  = {0,50,150,250,322,394,466};
    int t = threadIdx.x;
    for(int a=0;a<7;a++){
        for(int i=t;i<cnt[a];i+=blockDim.x)
            g_w[off[a]+i] = sp10(src[a][i]);
    }
    __syncthreads();
    if(t==0){
        const int ncout[7] = {2,2,2,2,2,2,1};
        const int per[7]   = {25,50,50,36,36,36,2};
        const int soff[7]  = {468,470,472,474,476,478,480};
        for(int a=0;a<7;a++){
            for(int co=0;co<ncout[a];co++){
                float s=0.f;
                for(int i=0;i<per[a];i++) s += g_w[off[a]+co*per[a]+i];
                g_w[soff[a]+co]=s;
            }
        }
    }
}

// ---------------- tiled 5x5 normalized conv, packed f32x2 ----------------
// Block 256 threads, 64x16 output tile, 2x2 quad per thread.
// smem stores (c, x*c) as float2; accumulators are packed (den, nom).
#define TX5 64
#define TY5 16
#define SW5 (TX5+4)   // 68
#define SH5 (TY5+4)   // 20

template<int CIN>
__global__ void __launch_bounds__(256)
k_nconv5t(const float* __restrict__ xin, const float* __restrict__ cin,
          const float* __restrict__ w,  const float* __restrict__ wsum,
          const float* __restrict__ bias,
          float* __restrict__ xout, float* __restrict__ cout_,
          int H, int W, int bpr, int bpc){
    __shared__ __align__(16) float2 sm[CIN][SH5*SW5];
    __shared__ ull  wpk[2*CIN*25];
    __shared__ float wex[4];

    const int t = threadIdx.x;
    const int P = H*W;

    for(int i=t;i<2*CIN*25;i+=256){
        float ww = w[i];
        float2 f2 = make_float2(ww, ww);
        wpk[i] = *(ull*)&f2;
    }
    if(t<2){ wex[t]=wsum[t]; wex[2+t]=bias[t]; }

    int bx = blockIdx.x % bpr;
    int tmp = blockIdx.x / bpr;
    int by = tmp % bpc;
    int b  = tmp / bpc;
    int gx0 = bx*TX5 - 2;
    int gy0 = by*TY5 - 2;

    #pragma unroll
    for(int ci=0;ci<CIN;ci++){
        const float* cb = cin + (size_t)(b*CIN+ci)*P;
        const float* xb = xin + (size_t)(b*CIN+ci)*P;
        for(int i=t;i<SH5*SW5;i+=256){
            int lx = i % SW5, ly = i / SW5;
            int gx = gx0+lx, gy = gy0+ly;
            float c=0.f, d=0.f;
            if((unsigned)gx<(unsigned)W && (unsigned)gy<(unsigned)H){
                int o = gy*W+gx;
                c = cb[o]; d = xb[o]*c;
            }
            sm[ci][i] = make_float2(c, d);
        }
    }
    __syncthreads();

    const int tx = (t & 31)*2;
    const int ty = (t >> 5)*2;

    ull acc[2][2][2];
    #pragma unroll
    for(int a=0;a<2;a++)
      #pragma unroll
      for(int dy=0;dy<2;dy++)
        #pragma unroll
        for(int dx=0;dx<2;dx++) acc[a][dy][dx]=0ull;

    #pragma unroll
    for(int ci=0;ci<CIN;ci++){
        #pragma unroll
        for(int ky=0;ky<5;ky++){
            ull wa[5], wb[5];
            #pragma unroll
            for(int kx=0;kx<5;kx++){
                wa[kx] = wpk[ci*25+ky*5+kx];
                wb[kx] = wpk[CIN*25+ci*25+ky*5+kx];
            }
            #pragma unroll
            for(int dy=0;dy<2;dy++){
                const longlong2* p = (const longlong2*)&sm[ci][(ty+ky+dy)*SW5 + tx];
                ull v[6];
                {
                    longlong2 q;
                    q=p[0]; v[0]=(ull)q.x; v[1]=(ull)q.y;
                    q=p[1]; v[2]=(ull)q.x; v[3]=(ull)q.y;
                    q=p[2]; v[4]=(ull)q.x; v[5]=(ull)q.y;
                }
                #pragma unroll
                for(int kx=0;kx<5;kx++){
                    acc[0][dy][0]=fma2(wa[kx], v[kx],   acc[0][dy][0]);
                    acc[0][dy][1]=fma2(wa[kx], v[kx+1], acc[0][dy][1]);
                    acc[1][dy][0]=fma2(wb[kx], v[kx],   acc[1][dy][0]);
                    acc[1][dy][1]=fma2(wb[kx], v[kx+1], acc[1][dy][1]);
                }
            }
        }
    }

    float rs0 = 1.0f/wex[0];
    float rs1 = 1.0f/wex[1];
    float bi0 = wex[2];
    float bi1 = wex[3];
    int gx = bx*TX5 + tx;
    #pragma unroll
    for(int dy=0;dy<2;dy++){
        int gy = by*TY5 + ty + dy;
        if(gy>=H || gx>=W) continue;
        #pragma unroll
        for(int a=0;a<2;a++){
            float d0,n0,d1,n1;
            unpack2(acc[a][dy][0], d0, n0);
            unpack2(acc[a][dy][1], d1, n1);
            float bia = a ? bi1 : bi0;
            float rsa = a ? rs1 : rs0;
            float2 xo = make_float2(n0/(d0+EPSV)+bia, n1/(d1+EPSV)+bia);
            float2 co = make_float2(d0*rsa, d1*rsa);
            size_t o = (size_t)(b*2+a)*P + (size_t)gy*W + gx;
            *(float2*)&xout[o]  = xo;
            *(float2*)&cout_[o] = co;
        }
    }
}

// ---------------- tiled 3x3 cat nconv, packed f32x2 ----------------
#define TX3 64
#define TY3 16
#define SW3 (TX3+2)   // 66
#define SH3 (TY3+2)   // 18

template<bool UP_FIRST>
__global__ void __launch_bounds__(256)
k_nconv3t(const float* __restrict__ xa, const float* __restrict__ ca,
          const float* __restrict__ xb, const float* __restrict__ cb,
          const float* __restrict__ w,  const float* __restrict__ wsum,
          const float* __restrict__ bias,
          float* __restrict__ xout, float* __restrict__ cout_,
          int H, int W, int bpr, int bpc){
    __shared__ __align__(16) float2 sm[4][SH3*SW3];
    __shared__ ull  wpk[72];
    __shared__ float wex[4];

    const int t = threadIdx.x;
    const int P = H*W;
    const int Wh = W>>1, Ph = (W>>1)*(H>>1);

    for(int i=t;i<72;i+=256){
        float ww = w[i];
        float2 f2 = make_float2(ww, ww);
        wpk[i] = *(ull*)&f2;
    }
    if(t<2){ wex[t]=wsum[t]; wex[2+t]=bias[t]; }

    int bx = blockIdx.x % bpr;
    int tmp = blockIdx.x / bpr;
    int by = tmp % bpc;
    int b  = tmp / bpc;
    int gx0 = bx*TX3 - 1;
    int gy0 = by*TY3 - 1;

    #pragma unroll
    for(int ci=0;ci<4;ci++){
        const bool fromUp = UP_FIRST ? (ci<2) : (ci>=2);
        const int ch = fromUp ? (UP_FIRST ? ci : ci-2) : (UP_FIRST ? ci-2 : ci);
        const float* cs = fromUp ? (cb + (size_t)(b*2+ch)*Ph) : (ca + (size_t)(b*2+ch)*P);
        const float* xs = fromUp ? (xb + (size_t)(b*2+ch)*Ph) : (xa + (size_t)(b*2+ch)*P);
        for(int i=t;i<SH3*SW3;i+=256){
            int lx = i % SW3, ly = i / SW3;
            int gx = gx0+lx, gy = gy0+ly;
            float c=0.f, d=0.f;
            if((unsigned)gx<(unsigned)W && (unsigned)gy<(unsigned)H){
                int o = fromUp ? ((gy>>1)*Wh + (gx>>1)) : (gy*W+gx);
                c = cs[o]; d = xs[o]*c;
            }
            sm[ci][i] = make_float2(c, d);
        }
    }
    __syncthreads();

    const int tx = (t & 31)*2;
    const int ty = (t >> 5)*2;

    ull acc[2][2][2];
    #pragma unroll
    for(int a=0;a<2;a++)
      #pragma unroll
      for(int dy=0;dy<2;dy++)
        #pragma unroll
        for(int dx=0;dx<2;dx++) acc[a][dy][dx]=0ull;

    #pragma unroll
    for(int ci=0;ci<4;ci++){
        #pragma unroll
        for(int ky=0;ky<3;ky++){
            ull wa[3], wb[3];
            #pragma unroll
            for(int kx=0;kx<3;kx++){
                wa[kx] = wpk[ci*9+ky*3+kx];
                wb[kx] = wpk[36+ci*9+ky*3+kx];
            }
            #pragma unroll
            for(int dy=0;dy<2;dy++){
                const longlong2* p = (const longlong2*)&sm[ci][(ty+ky+dy)*SW3 + tx];
                ull v[4];
                {
                    longlong2 q;
                    q=p[0]; v[0]=(ull)q.x; v[1]=(ull)q.y;
                    q=p[1]; v[2]=(ull)q.x; v[3]=(ull)q.y;
                }
                #pragma unroll
                for(int kx=0;kx<3;kx++){
                    acc[0][dy][0]=fma2(wa[kx], v[kx],   acc[0][dy][0]);
                    acc[0][dy][1]=fma2(wa[kx], v[kx+1], acc[0][dy][1]);
                    acc[1][dy][0]=fma2(wb[kx], v[kx],   acc[1][dy][0]);
                    acc[1][dy][1]=fma2(wb[kx], v[kx+1], acc[1][dy][1]);
                }
            }
        }
    }

    float rs0 = 1.0f/wex[0];
    float rs1 = 1.0f/wex[1];
    float bi0 = wex[2];
    float bi1 = wex[3];
    int gx = bx*TX3 + tx;
    #pragma unroll
    for(int dy=0;dy<2;dy++){
        int gy = by*TY3 + ty + dy;
        if(gy>=H || gx>=W) continue;
        #pragma unroll
        for(int a=0;a<2;a++){
            float d0,n0,d1,n1;
            unpack2(acc[a][dy][0], d0, n0);
            unpack2(acc[a][dy][1], d1, n1);
            float bia = a ? bi1 : bi0;
            float rsa = a ? rs1 : rs0;
            float2 xo = make_float2(n0/(d0+EPSV)+bia, n1/(d1+EPSV)+bia);
            float2 co = make_float2(d0*rsa, d1*rsa);
            size_t o = (size_t)(b*2+a)*P + (size_t)gy*W + gx;
            *(float2*)&xout[o]  = xo;
            *(float2*)&cout_[o] = co;
        }
    }
}

// 2x2 max-pool on conf (first-max, row-major order), gather x at argmax.
__global__ void k_pool(const float* __restrict__ cin, const float* __restrict__ xin,
                       float* __restrict__ cds, float* __restrict__ xds,
                       int Hh, int Wh){
    int idx = blockIdx.x*blockDim.x + threadIdx.x;
    int total = BB*2*Hh*Wh;
    if(idx >= total) return;
    int x = idx % Wh;
    int y = (idx / Wh) % Hh;
    int pl = idx / (Hh*Wh);
    int Wi = Wh*2;
    size_t base = (size_t)pl*(Hh*2)*Wi + (size_t)(2*y)*Wi + 2*x;
    float2 ct = *(const float2*)(cin+base);
    float2 cbm= *(const float2*)(cin+base+Wi);
    float2 xt = *(const float2*)(xin+base);
    float2 xbm= *(const float2*)(xin+base+Wi);
    float best=ct.x, bx=xt.x;
    if(ct.y >best){best=ct.y; bx=xt.y;}
    if(cbm.x>best){best=cbm.x;bx=xbm.x;}
    if(cbm.y>best){best=cbm.y;bx=xbm.y;}
    cds[idx]=best*0.25f;
    xds[idx]=bx;
}

// final 1x1 nconv, float4-vectorized
__global__ void k_nconv1x1(const float* __restrict__ xin, const float* __restrict__ cin,
                           const float* __restrict__ w, const float* __restrict__ wsum,
                           const float* __restrict__ bias,
                           float* __restrict__ xout, float* __restrict__ cout_){
    int idx = blockIdx.x*blockDim.x + threadIdx.x;
    const int Q = P0/4;
    if(idx >= BB*Q) return;
    int q = idx % Q;
    int b = idx / Q;
    const float4* x0p = (const float4*)(xin + (size_t)(b*2+0)*P0) + q;
    const float4* x1p = (const float4*)(xin + (size_t)(b*2+1)*P0) + q;
    const float4* c0p = (const float4*)(cin + (size_t)(b*2+0)*P0) + q;
    const float4* c1p = (const float4*)(cin + (size_t)(b*2+1)*P0) + q;
    float4 X0=*x0p, X1=*x1p, C0=*c0p, C1=*c1p;
    float w0=w[0], w1=w[1];
    float rsum = 1.0f/wsum[0];
    float bi = bias[0];
    float4 XO, CO;
    #pragma unroll
    for(int k=0;k<4;k++){
        float c0v = ((const float*)&C0)[k];
        float c1v = ((const float*)&C1)[k];
        float den = w0*c0v + w1*c1v;
        float nom = w0*(((const float*)&X0)[k]*c0v) + w1*(((const float*)&X1)[k]*c1v);
        ((float*)&XO)[k] = nom/(den+EPSV) + bi;
        ((float*)&CO)[k] = den*rsum;
    }
    ((float4*)(xout  + (size_t)b*P0))[q] = XO;
    ((float4*)(cout_ + (size_t)b*P0))[q] = CO;
}

extern "C" void kernel_launch(void* const* d_in, const int* in_sizes, int n_in,
                              void* d_out, int out_size){
    const float* x0 = (const float*)d_in[0];
    const float* c0 = (const float*)d_in[1];
    const float* w1 = (const float*)d_in[2];  const float* b1 = (const float*)d_in[3];
    const float* w2 = (const float*)d_in[4];  const float* b2 = (const float*)d_in[5];
    const float* w3 = (const float*)d_in[6];  const float* b3 = (const float*)d_in[7];
    const float* w4 = (const float*)d_in[8];  const float* b4 = (const float*)d_in[9];
    const float* w5 = (const float*)d_in[10]; const float* b5 = (const float*)d_in[11];
    const float* w6 = (const float*)d_in[12]; const float* b6 = (const float*)d_in[13];
    const float* w7 = (const float*)d_in[14]; const float* b7 = (const float*)d_in[15];

    float* S = nullptr;  cudaGetSymbolAddress((void**)&S,  g_scratch);
    float* Wt = nullptr; cudaGetSymbolAddress((void**)&Wt, g_w);

    float *xA=S,   *cA=S+N0,   *xB=S+2*N0, *cB=S+3*N0, *x1=S+4*N0, *c1=S+5*N0;
    float *Sh = S + 6*N0;
    float *xha=Sh, *cha=Sh+N1, *xhb=Sh+2*N1, *chb=Sh+3*N1, *x2d=Sh+4*N1, *c2d=Sh+5*N1;
    float *Sq = Sh + 6*N1;
    float *xq=Sq,  *cq=Sq+N2,  *x3d=Sq+2*N2, *c3d=Sq+3*N2, *x34=Sq+4*N2, *c34=Sq+5*N2;
    float *Se = Sq + 6*N2;
    float *xe=Se,  *ce=Se+N3,  *x4=Se+2*N3,  *c4=Se+3*N3;

    const int thr = 256;
    auto gb = [&](long n){ return (int)((n + thr - 1) / thr); };
    auto tiles = [&](int H, int W, int &bpr, int &bpc)->int{
        bpr = (W + TX5 - 1)/TX5; bpc = (H + TY5 - 1)/TY5;
        return bpr*bpc*BB;
    };

    k_prep<<<1,128>>>(w1,w2,w3,w4,w5,w6,w7);

    int bpr, bpc, g;

    // encoder full res
    g = tiles(H0,W0,bpr,bpc);
    k_nconv5t<1><<<g,thr>>>(x0, c0, Wt+0,   Wt+468, b1, xA, cA, H0, W0, bpr, bpc);
    k_nconv5t<2><<<g,thr>>>(xA, cA, Wt+50,  Wt+470, b2, xB, cB, H0, W0, bpr, bpc);
    k_nconv5t<2><<<g,thr>>>(xB, cB, Wt+150, Wt+472, b3, x1, c1, H0, W0, bpr, bpc);

    // level 1
    k_pool<<<gb((long)BB*2*P1),thr>>>(c1, x1, cha, xha, H1, W1);
    g = tiles(H1,W1,bpr,bpc);
    k_nconv5t<2><<<g,thr>>>(xha, cha, Wt+50,  Wt+470, b2, xhb, chb, H1, W1, bpr, bpc);
    k_nconv5t<2><<<g,thr>>>(xhb, chb, Wt+150, Wt+472, b3, x2d, c2d, H1, W1, bpr, bpc);

    // level 2
    k_pool<<<gb((long)BB*2*P2),thr>>>(c2d, x2d, cq, xq, H2, W2);
    g = tiles(H2,W2,bpr,bpc);
    k_nconv5t<2><<<g,thr>>>(xq, cq, Wt+50, Wt+470, b2, x3d, c3d, H2, W2, bpr, bpc);

    // level 3
    k_pool<<<gb((long)BB*2*P3),thr>>>(c3d, x3d, ce, xe, H3, W3);
    g = tiles(H3,W3,bpr,bpc);
    k_nconv5t<2><<<g,thr>>>(xe, ce, Wt+50, Wt+470, b2, x4, c4, H3, W3, bpr, bpc);

    // decoder
    g = tiles(H2,W2,bpr,bpc);
    k_nconv3t<false><<<g,thr>>>(x3d, c3d, x4, c4,  Wt+250, Wt+474, b4, x34, c34, H2, W2, bpr, bpc);
    g = tiles(H1,W1,bpr,bpc);
    k_nconv3t<false><<<g,thr>>>(x2d, c2d, x34, c34, Wt+322, Wt+476, b5, xha, cha, H1, W1, bpr, bpc);
    g = tiles(H0,W0,bpr,bpc);
    k_nconv3t<true><<<g,thr>>>(x1, c1, xha, cha,   Wt+394, Wt+478, b6, xA, cA, H0, W0, bpr, bpc);

    float* out = (float*)d_out;
    k_nconv1x1<<<gb((long)BB*(P0/4)),thr>>>(xA, cA, Wt+466, Wt+480, b7,
                                            out, out + (size_t)BB*P0);
}

// round 4
// speedup vs baseline: 1.8494x; 1.0333x over previous
#include <cuda_runtime.h>
#include <math.h>

#define EPSV 1e-20f

#define BB 16
#define H0 352
#define W0 1216
#define H1 176
#define W1 608
#define H2 88
#define W2 304
#define H3 44
#define W3 152

#define P0 (H0*W0)
#define P1 (H1*W1)
#define P2 (H2*W2)
#define P3 (H3*W3)

#define N0 ((size_t)BB*2*P0)
#define N1 ((size_t)BB*2*P1)
#define N2 ((size_t)BB*2*P2)
#define N3 ((size_t)BB*2*P3)

__device__ float g_scratch[6*N0 + 6*N1 + 6*N2 + 4*N3];
__device__ float g_w[512];

// weight offsets: w1:0(50) w2:50(100) w3:150(100) w4:250(72) w5:322(72) w6:394(72) w7:466(2)
// sums: s1:468 s2:470 s3:472 s4:474 s5:476 s6:478 s7:480

typedef unsigned long long ull;

__device__ __forceinline__ ull fma2(ull a, ull b, ull c){
    ull d; asm("fma.rn.f32x2 %0, %1, %2, %3;" : "=l"(d) : "l"(a), "l"(b), "l"(c)); return d;
}
__device__ __forceinline__ void unpack2(ull v, float &a, float &b){
    asm("mov.b64 {%0,%1}, %2;" : "=f"(a), "=f"(b) : "l"(v));
}

__device__ __forceinline__ float sp10(float p){
    float z = 10.0f * p;
    float r = (z > 20.0f) ? z : log1pf(expf(z));
    return r * 0.1f;
}

__global__ void k_prep(const float* __restrict__ w1, const float* __restrict__ w2,
                       const float* __restrict__ w3, const float* __restrict__ w4,
                       const float* __restrict__ w5, const float* __restrict__ w6,
                       const float* __restrict__ w7){
    const float* src[7] = {w1,w2,w3,w4,w5,w6,w7};
    const int   cnt[7]  = {50,100,100,72,72,72,2};
    const int   off[7]  = {0,50,150,250,322,394,466};
    int t = threadIdx.x;
    for(int a=0;a<7;a++){
        for(int i=t;i<cnt[a];i+=blockDim.x)
            g_w[off[a]+i] = sp10(src[a][i]);
    }
    __syncthreads();
    if(t==0){
        const int ncout[7] = {2,2,2,2,2,2,1};
        const int per[7]   = {25,50,50,36,36,36,2};
        const int soff[7]  = {468,470,472,474,476,478,480};
        for(int a=0;a<7;a++){
            for(int co=0;co<ncout[a];co++){
                float s=0.f;
                for(int i=0;i<per[a];i++) s += g_w[off[a]+co*per[a]+i];
                g_w[soff[a]+co]=s;
            }
        }
    }
}

// ---------------- tiled 5x5 normalized conv, packed f32x2, 4x2 per thread --
// Block 256 threads (16x16), output tile 64x32.
#define TX5 64
#define TY5 32
#define SW5 (TX5+4)   // 68
#define SH5 (TY5+4)   // 36

template<int CIN>
__global__ void __launch_bounds__(256)
k_nconv5t(const float* __restrict__ xin, const float* __restrict__ cin,
          const float* __restrict__ w,  const float* __restrict__ wsum,
          const float* __restrict__ bias,
          float* __restrict__ xout, float* __restrict__ cout_,
          int H, int W, int bpr, int bpc){
    __shared__ __align__(16) float2 sm[CIN][SH5*SW5];
    __shared__ ull  wpk[2*CIN*25];
    __shared__ float wex[4];

    const int t = threadIdx.x;
    const int P = H*W;

    for(int i=t;i<2*CIN*25;i+=256){
        float ww = w[i];
        float2 f2 = make_float2(ww, ww);
        wpk[i] = *(ull*)&f2;
    }
    if(t<2){ wex[t]=wsum[t]; wex[2+t]=bias[t]; }

    int bx = blockIdx.x % bpr;
    int tmp = blockIdx.x / bpr;
    int by = tmp % bpc;
    int b  = tmp / bpc;
    int gx0 = bx*TX5 - 2;
    int gy0 = by*TY5 - 2;

    #pragma unroll
    for(int ci=0;ci<CIN;ci++){
        const float* cb = cin + (size_t)(b*CIN+ci)*P;
        const float* xb = xin + (size_t)(b*CIN+ci)*P;
        for(int i=t;i<SH5*SW5;i+=256){
            int lx = i % SW5, ly = i / SW5;
            int gx = gx0+lx, gy = gy0+ly;
            float c=0.f, d=0.f;
            if((unsigned)gx<(unsigned)W && (unsigned)gy<(unsigned)H){
                int o = gy*W+gx;
                c = cb[o]; d = xb[o]*c;
            }
            sm[ci][i] = make_float2(c, d);
        }
    }
    __syncthreads();

    const int tx = (t & 15)*4;
    const int ty = (t >> 4)*2;

    ull acc[2][2][4];
    #pragma unroll
    for(int a=0;a<2;a++)
      #pragma unroll
      for(int dy=0;dy<2;dy++)
        #pragma unroll
        for(int dx=0;dx<4;dx++) acc[a][dy][dx]=0ull;

    #pragma unroll
    for(int ci=0;ci<CIN;ci++){
        #pragma unroll
        for(int ky=0;ky<5;ky++){
            ull wa[5], wb[5];
            #pragma unroll
            for(int kx=0;kx<5;kx++){
                wa[kx] = wpk[ci*25+ky*5+kx];
                wb[kx] = wpk[CIN*25+ci*25+ky*5+kx];
            }
            #pragma unroll
            for(int dy=0;dy<2;dy++){
                const longlong2* p = (const longlong2*)&sm[ci][(ty+ky+dy)*SW5 + tx];
                ull v[8];
                #pragma unroll
                for(int j=0;j<4;j++){
                    longlong2 q = p[j];
                    v[2*j]=(ull)q.x; v[2*j+1]=(ull)q.y;
                }
                #pragma unroll
                for(int kx=0;kx<5;kx++){
                    #pragma unroll
                    for(int dx=0;dx<4;dx++){
                        acc[0][dy][dx]=fma2(wa[kx], v[kx+dx], acc[0][dy][dx]);
                        acc[1][dy][dx]=fma2(wb[kx], v[kx+dx], acc[1][dy][dx]);
                    }
                }
            }
        }
    }

    float rs0 = 1.0f/wex[0];
    float rs1 = 1.0f/wex[1];
    float bi0 = wex[2];
    float bi1 = wex[3];
    int gx = bx*TX5 + tx;
    if(gx < W){
        #pragma unroll
        for(int dy=0;dy<2;dy++){
            int gy = by*TY5 + ty + dy;
            if(gy>=H) continue;
            #pragma unroll
            for(int a=0;a<2;a++){
                float d0,n0,d1,n1,d2,n2,d3,n3;
                unpack2(acc[a][dy][0], d0, n0);
                unpack2(acc[a][dy][1], d1, n1);
                unpack2(acc[a][dy][2], d2, n2);
                unpack2(acc[a][dy][3], d3, n3);
                float bia = a ? bi1 : bi0;
                float rsa = a ? rs1 : rs0;
                float4 xo = make_float4(n0/(d0+EPSV)+bia, n1/(d1+EPSV)+bia,
                                        n2/(d2+EPSV)+bia, n3/(d3+EPSV)+bia);
                float4 co = make_float4(d0*rsa, d1*rsa, d2*rsa, d3*rsa);
                size_t o = (size_t)(b*2+a)*P + (size_t)gy*W + gx;
                *(float4*)&xout[o]  = xo;
                *(float4*)&cout_[o] = co;
            }
        }
    }
}

// ---------------- tiled 3x3 cat nconv, packed f32x2, 4x2 per thread --------
// Block 128 threads (16x8), output tile 64x16.
#define TX3 64
#define TY3 16
#define SW3 (TX3+2)   // 66
#define SH3 (TY3+2)   // 18

template<bool UP_FIRST>
__global__ void __launch_bounds__(128)
k_nconv3t(const float* __restrict__ xa, const float* __restrict__ ca,
          const float* __restrict__ xb, const float* __restrict__ cb,
          const float* __restrict__ w,  const float* __restrict__ wsum,
          const float* __restrict__ bias,
          float* __restrict__ xout, float* __restrict__ cout_,
          int H, int W, int bpr, int bpc){
    __shared__ __align__(16) float2 sm[4][SH3*SW3];
    __shared__ ull  wpk[72];
    __shared__ float wex[4];

    const int t = threadIdx.x;
    const int P = H*W;
    const int Wh = W>>1, Ph = (W>>1)*(H>>1);

    for(int i=t;i<72;i+=128){
        float ww = w[i];
        float2 f2 = make_float2(ww, ww);
        wpk[i] = *(ull*)&f2;
    }
    if(t<2){ wex[t]=wsum[t]; wex[2+t]=bias[t]; }

    int bx = blockIdx.x % bpr;
    int tmp = blockIdx.x / bpr;
    int by = tmp % bpc;
    int b  = tmp / bpc;
    int gx0 = bx*TX3 - 1;
    int gy0 = by*TY3 - 1;

    #pragma unroll
    for(int ci=0;ci<4;ci++){
        const bool fromUp = UP_FIRST ? (ci<2) : (ci>=2);
        const int ch = fromUp ? (UP_FIRST ? ci : ci-2) : (UP_FIRST ? ci-2 : ci);
        const float* cs = fromUp ? (cb + (size_t)(b*2+ch)*Ph) : (ca + (size_t)(b*2+ch)*P);
        const float* xs = fromUp ? (xb + (size_t)(b*2+ch)*Ph) : (xa + (size_t)(b*2+ch)*P);
        for(int i=t;i<SH3*SW3;i+=128){
            int lx = i % SW3, ly = i / SW3;
            int gx = gx0+lx, gy = gy0+ly;
            float c=0.f, d=0.f;
            if((unsigned)gx<(unsigned)W && (unsigned)gy<(unsigned)H){
                int o = fromUp ? ((gy>>1)*Wh + (gx>>1)) : (gy*W+gx);
                c = cs[o]; d = xs[o]*c;
            }
            sm[ci][i] = make_float2(c, d);
        }
    }
    __syncthreads();

    const int tx = (t & 15)*4;
    const int ty = (t >> 4)*2;

    ull acc[2][2][4];
    #pragma unroll
    for(int a=0;a<2;a++)
      #pragma unroll
      for(int dy=0;dy<2;dy++)
        #pragma unroll
        for(int dx=0;dx<4;dx++) acc[a][dy][dx]=0ull;

    #pragma unroll
    for(int ci=0;ci<4;ci++){
        #pragma unroll
        for(int ky=0;ky<3;ky++){
            ull wa[3], wb[3];
            #pragma unroll
            for(int kx=0;kx<3;kx++){
                wa[kx] = wpk[ci*9+ky*3+kx];
                wb[kx] = wpk[36+ci*9+ky*3+kx];
            }
            #pragma unroll
            for(int dy=0;dy<2;dy++){
                const longlong2* p = (const longlong2*)&sm[ci][(ty+ky+dy)*SW3 + tx];
                ull v[6];
                #pragma unroll
                for(int j=0;j<3;j++){
                    longlong2 q = p[j];
                    v[2*j]=(ull)q.x; v[2*j+1]=(ull)q.y;
                }
                #pragma unroll
                for(int kx=0;kx<3;kx++){
                    #pragma unroll
                    for(int dx=0;dx<4;dx++){
                        acc[0][dy][dx]=fma2(wa[kx], v[kx+dx], acc[0][dy][dx]);
                        acc[1][dy][dx]=fma2(wb[kx], v[kx+dx], acc[1][dy][dx]);
                    }
                }
            }
        }
    }

    float rs0 = 1.0f/wex[0];
    float rs1 = 1.0f/wex[1];
    float bi0 = wex[2];
    float bi1 = wex[3];
    int gx = bx*TX3 + tx;
    if(gx < W){
        #pragma unroll
        for(int dy=0;dy<2;dy++){
            int gy = by*TY3 + ty + dy;
            if(gy>=H) continue;
            #pragma unroll
            for(int a=0;a<2;a++){
                float d0,n0,d1,n1,d2,n2,d3,n3;
                unpack2(acc[a][dy][0], d0, n0);
                unpack2(acc[a][dy][1], d1, n1);
                unpack2(acc[a][dy][2], d2, n2);
                unpack2(acc[a][dy][3], d3, n3);
                float bia = a ? bi1 : bi0;
                float rsa = a ? rs1 : rs0;
                float4 xo = make_float4(n0/(d0+EPSV)+bia, n1/(d1+EPSV)+bia,
                                        n2/(d2+EPSV)+bia, n3/(d3+EPSV)+bia);
                float4 co = make_float4(d0*rsa, d1*rsa, d2*rsa, d3*rsa);
                size_t o = (size_t)(b*2+a)*P + (size_t)gy*W + gx;
                *(float4*)&xout[o]  = xo;
                *(float4*)&cout_[o] = co;
            }
        }
    }
}

// 2x2 max-pool on conf (first-max, row-major order), gather x at argmax.
__global__ void k_pool(const float* __restrict__ cin, const float* __restrict__ xin,
                       float* __restrict__ cds, float* __restrict__ xds,
                       int Hh, int Wh){
    int idx = blockIdx.x*blockDim.x + threadIdx.x;
    int total = BB*2*Hh*Wh;
    if(idx >= total) return;
    int x = idx % Wh;
    int y = (idx / Wh) % Hh;
    int pl = idx / (Hh*Wh);
    int Wi = Wh*2;
    size_t base = (size_t)pl*(Hh*2)*Wi + (size_t)(2*y)*Wi + 2*x;
    float2 ct = *(const float2*)(cin+base);
    float2 cbm= *(const float2*)(cin+base+Wi);
    float2 xt = *(const float2*)(xin+base);
    float2 xbm= *(const float2*)(xin+base+Wi);
    float best=ct.x, bx=xt.x;
    if(ct.y >best){best=ct.y; bx=xt.y;}
    if(cbm.x>best){best=cbm.x;bx=xbm.x;}
    if(cbm.y>best){best=cbm.y;bx=xbm.y;}
    cds[idx]=best*0.25f;
    xds[idx]=bx;
}

// final 1x1 nconv, float4-vectorized
__global__ void k_nconv1x1(const float* __restrict__ xin, const float* __restrict__ cin,
                           const float* __restrict__ w, const float* __restrict__ wsum,
                           const float* __restrict__ bias,
                           float* __restrict__ xout, float* __restrict__ cout_){
    int idx = blockIdx.x*blockDim.x + threadIdx.x;
    const int Q = P0/4;
    if(idx >= BB*Q) return;
    int q = idx % Q;
    int b = idx / Q;
    const float4* x0p = (const float4*)(xin + (size_t)(b*2+0)*P0) + q;
    const float4* x1p = (const float4*)(xin + (size_t)(b*2+1)*P0) + q;
    const float4* c0p = (const float4*)(cin + (size_t)(b*2+0)*P0) + q;
    const float4* c1p = (const float4*)(cin + (size_t)(b*2+1)*P0) + q;
    float4 X0=*x0p, X1=*x1p, C0=*c0p, C1=*c1p;
    float w0=w[0], w1=w[1];
    float rsum = 1.0f/wsum[0];
    float bi = bias[0];
    float4 XO, CO;
    #pragma unroll
    for(int k=0;k<4;k++){
        float c0v = ((const float*)&C0)[k];
        float c1v = ((const float*)&C1)[k];
        float den = w0*c0v + w1*c1v;
        float nom = w0*(((const float*)&X0)[k]*c0v) + w1*(((const float*)&X1)[k]*c1v);
        ((float*)&XO)[k] = nom/(den+EPSV) + bi;
        ((float*)&CO)[k] = den*rsum;
    }
    ((float4*)(xout  + (size_t)b*P0))[q] = XO;
    ((float4*)(cout_ + (size_t)b*P0))[q] = CO;
}

extern "C" void kernel_launch(void* const* d_in, const int* in_sizes, int n_in,
                              void* d_out, int out_size){
    const float* x0 = (const float*)d_in[0];
    const float* c0 = (const float*)d_in[1];
    const float* w1 = (const float*)d_in[2];  const float* b1 = (const float*)d_in[3];
    const float* w2 = (const float*)d_in[4];  const float* b2 = (const float*)d_in[5];
    const float* w3 = (const float*)d_in[6];  const float* b3 = (const float*)d_in[7];
    const float* w4 = (const float*)d_in[8];  const float* b4 = (const float*)d_in[9];
    const float* w5 = (const float*)d_in[10]; const float* b5 = (const float*)d_in[11];
    const float* w6 = (const float*)d_in[12]; const float* b6 = (const float*)d_in[13];
    const float* w7 = (const float*)d_in[14]; const float* b7 = (const float*)d_in[15];

    float* S = nullptr;  cudaGetSymbolAddress((void**)&S,  g_scratch);
    float* Wt = nullptr; cudaGetSymbolAddress((void**)&Wt, g_w);

    float *xA=S,   *cA=S+N0,   *xB=S+2*N0, *cB=S+3*N0, *x1=S+4*N0, *c1=S+5*N0;
    float *Sh = S + 6*N0;
    float *xha=Sh, *cha=Sh+N1, *xhb=Sh+2*N1, *chb=Sh+3*N1, *x2d=Sh+4*N1, *c2d=Sh+5*N1;
    float *Sq = Sh + 6*N1;
    float *xq=Sq,  *cq=Sq+N2,  *x3d=Sq+2*N2, *c3d=Sq+3*N2, *x34=Sq+4*N2, *c34=Sq+5*N2;
    float *Se = Sq + 6*N2;
    float *xe=Se,  *ce=Se+N3,  *x4=Se+2*N3,  *c4=Se+3*N3;

    const int thr = 256;
    auto gb = [&](long n){ return (int)((n + thr - 1) / thr); };
    auto tiles5 = [&](int H, int W, int &bpr, int &bpc)->int{
        bpr = (W + TX5 - 1)/TX5; bpc = (H + TY5 - 1)/TY5;
        return bpr*bpc*BB;
    };
    auto tiles3 = [&](int H, int W, int &bpr, int &bpc)->int{
        bpr = (W + TX3 - 1)/TX3; bpc = (H + TY3 - 1)/TY3;
        return bpr*bpc*BB;
    };

    k_prep<<<1,128>>>(w1,w2,w3,w4,w5,w6,w7);

    int bpr, bpc, g;

    // encoder full res
    g = tiles5(H0,W0,bpr,bpc);
    k_nconv5t<1><<<g,256>>>(x0, c0, Wt+0,   Wt+468, b1, xA, cA, H0, W0, bpr, bpc);
    k_nconv5t<2><<<g,256>>>(xA, cA, Wt+50,  Wt+470, b2, xB, cB, H0, W0, bpr, bpc);
    k_nconv5t<2><<<g,256>>>(xB, cB, Wt+150, Wt+472, b3, x1, c1, H0, W0, bpr, bpc);

    // level 1
    k_pool<<<gb((long)BB*2*P1),thr>>>(c1, x1, cha, xha, H1, W1);
    g = tiles5(H1,W1,bpr,bpc);
    k_nconv5t<2><<<g,256>>>(xha, cha, Wt+50,  Wt+470, b2, xhb, chb, H1, W1, bpr, bpc);
    k_nconv5t<2><<<g,256>>>(xhb, chb, Wt+150, Wt+472, b3, x2d, c2d, H1, W1, bpr, bpc);

    // level 2
    k_pool<<<gb((long)BB*2*P2),thr>>>(c2d, x2d, cq, xq, H2, W2);
    g = tiles5(H2,W2,bpr,bpc);
    k_nconv5t<2><<<g,256>>>(xq, cq, Wt+50, Wt+470, b2, x3d, c3d, H2, W2, bpr, bpc);

    // level 3
    k_pool<<<gb((long)BB*2*P3),thr>>>(c3d, x3d, ce, xe, H3, W3);
    g = tiles5(H3,W3,bpr,bpc);
    k_nconv5t<2><<<g,256>>>(xe, ce, Wt+50, Wt+470, b2, x4, c4, H3, W3, bpr, bpc);

    // decoder
    g = tiles3(H2,W2,bpr,bpc);
    k_nconv3t<false><<<g,128>>>(x3d, c3d, x4, c4,  Wt+250, Wt+474, b4, x34, c34, H2, W2, bpr, bpc);
    g = tiles3(H1,W1,bpr,bpc);
    k_nconv3t<false><<<g,128>>>(x2d, c2d, x34, c34, Wt+322, Wt+476, b5, xha, cha, H1, W1, bpr, bpc);
    g = tiles3(H0,W0,bpr,bpc);
    k_nconv3t<true><<<g,128>>>(x1, c1, xha, cha,   Wt+394, Wt+478, b6, xA, cA, H0, W0, bpr, bpc);

    float* out = (float*)d_out;
    k_nconv1x1<<<gb((long)BB*(P0/4)),thr>>>(xA, cA, Wt+466, Wt+480, b7,
                                            out, out + (size_t)BB*P0);
}

// round 5
// speedup vs baseline: 1.9521x; 1.0555x over previous
#include <cuda_runtime.h>
#include <math.h>

#define EPSV 1e-20f

#define BB 16
#define H0 352
#define W0 1216
#define H1 176
#define W1 608
#define H2 88
#define W2 304
#define H3 44
#define W3 152

#define P0 (H0*W0)
#define P1 (H1*W1)
#define P2 (H2*W2)
#define P3 (H3*W3)

#define N0 ((size_t)BB*2*P0)
#define N1 ((size_t)BB*2*P1)
#define N2 ((size_t)BB*2*P2)
#define N3 ((size_t)BB*2*P3)

__device__ float g_scratch[6*N0 + 6*N1 + 6*N2 + 4*N3];
__device__ float g_w[512];

// weight offsets: w1:0(50) w2:50(100) w3:150(100) w4:250(72) w5:322(72) w6:394(72) w7:466(2)
// sums: s1:468 s2:470 s3:472 s4:474 s5:476 s6:478 s7:480

typedef unsigned long long ull;

__device__ __forceinline__ ull fma2(ull a, ull b, ull c){
    ull d; asm("fma.rn.f32x2 %0, %1, %2, %3;" : "=l"(d) : "l"(a), "l"(b), "l"(c)); return d;
}
__device__ __forceinline__ void unpack2(ull v, float &a, float &b){
    asm("mov.b64 {%0,%1}, %2;" : "=f"(a), "=f"(b) : "l"(v));
}
__device__ __forceinline__ ull dupf(float w){
    float2 f2 = make_float2(w, w);
    return *(ull*)&f2;
}

__device__ __forceinline__ float sp10(float p){
    float z = 10.0f * p;
    float r = (z > 20.0f) ? z : log1pf(expf(z));
    return r * 0.1f;
}

__global__ void k_prep(const float* __restrict__ w1, const float* __restrict__ w2,
                       const float* __restrict__ w3, const float* __restrict__ w4,
                       const float* __restrict__ w5, const float* __restrict__ w6,
                       const float* __restrict__ w7){
    const float* src[7] = {w1,w2,w3,w4,w5,w6,w7};
    const int   cnt[7]  = {50,100,100,72,72,72,2};
    const int   off[7]  = {0,50,150,250,322,394,466};
    int t = threadIdx.x;
    for(int a=0;a<7;a++){
        for(int i=t;i<cnt[a];i+=blockDim.x)
            g_w[off[a]+i] = sp10(src[a][i]);
    }
    __syncthreads();
    if(t==0){
        const int ncout[7] = {2,2,2,2,2,2,1};
        const int per[7]   = {25,50,50,36,36,36,2};
        const int soff[7]  = {468,470,472,474,476,478,480};
        for(int a=0;a<7;a++){
            for(int co=0;co<ncout[a];co++){
                float s=0.f;
                for(int i=0;i<per[a];i++) s += g_w[off[a]+co*per[a]+i];
                g_w[soff[a]+co]=s;
            }
        }
    }
}

// ---------------- tiled 5x5 nconv, packed f32x2, row-once, 4x2/thread -----
// Block = 128 threads (16x8), output tile 64x16.
#define TX5 64
#define TY5 16
#define SW5 (TX5+4)   // 68
#define SH5 (TY5+4)   // 20

template<int CIN>
__global__ void __launch_bounds__(128)
k_nconv5t(const float* __restrict__ xin, const float* __restrict__ cin,
          const float* __restrict__ w,  const float* __restrict__ wsum,
          const float* __restrict__ bias,
          float* __restrict__ xout, float* __restrict__ cout_,
          int H, int W, int bpr, int bpc){
    __shared__ __align__(16) float2 sm[CIN][SH5*SW5];
    __shared__ __align__(16) ull  wpk2[2*CIN*25];   // interleaved (cout0,cout1) dup pairs
    __shared__ float wex[4];

    const int t = threadIdx.x;
    const int P = H*W;

    for(int i=t;i<CIN*25;i+=128){
        wpk2[2*i]   = dupf(w[i]);
        wpk2[2*i+1] = dupf(w[CIN*25+i]);
    }
    if(t<2){ wex[t]=wsum[t]; wex[2+t]=bias[t]; }

    int bx = blockIdx.x % bpr;
    int tmp = blockIdx.x / bpr;
    int by = tmp % bpc;
    int b  = tmp / bpc;
    int gx0 = bx*TX5 - 2;
    int gy0 = by*TY5 - 2;

    #pragma unroll
    for(int ci=0;ci<CIN;ci++){
        const float* cb = cin + (size_t)(b*CIN+ci)*P;
        const float* xb = xin + (size_t)(b*CIN+ci)*P;
        for(int i=t;i<SH5*SW5;i+=128){
            int lx = i % SW5, ly = i / SW5;
            int gx = gx0+lx, gy = gy0+ly;
            float c=0.f, d=0.f;
            if((unsigned)gx<(unsigned)W && (unsigned)gy<(unsigned)H){
                int o = gy*W+gx;
                c = cb[o]; d = xb[o]*c;
            }
            sm[ci][i] = make_float2(c, d);
        }
    }
    __syncthreads();

    const int tx = (t & 15)*4;
    const int ty = (t >> 4)*2;

    ull acc[2][2][4];
    #pragma unroll
    for(int a=0;a<2;a++)
      #pragma unroll
      for(int dy=0;dy<2;dy++)
        #pragma unroll
        for(int dx=0;dx<4;dx++) acc[a][dy][dx]=0ull;

    #pragma unroll
    for(int ci=0;ci<CIN;ci++){
        ull v[8];
        {
            const longlong2* p = (const longlong2*)&sm[ci][ty*SW5 + tx];
            #pragma unroll
            for(int j=0;j<4;j++){ longlong2 q=p[j]; v[2*j]=(ull)q.x; v[2*j+1]=(ull)q.y; }
        }
        #pragma unroll
        for(int r=0;r<6;r++){
            ull vn[8];
            if(r<5){
                const longlong2* p = (const longlong2*)&sm[ci][(ty+r+1)*SW5 + tx];
                #pragma unroll
                for(int j=0;j<4;j++){ longlong2 q=p[j]; vn[2*j]=(ull)q.x; vn[2*j+1]=(ull)q.y; }
            }
            #pragma unroll
            for(int dy=0;dy<2;dy++){
                int ky = r - dy;
                if(ky>=0 && ky<=4){
                    #pragma unroll
                    for(int kx=0;kx<5;kx++){
                        longlong2 wp = *(const longlong2*)&wpk2[(ci*25+ky*5+kx)*2];
                        ull wa=(ull)wp.x, wb=(ull)wp.y;
                        #pragma unroll
                        for(int dx=0;dx<4;dx++){
                            acc[0][dy][dx]=fma2(wa, v[kx+dx], acc[0][dy][dx]);
                            acc[1][dy][dx]=fma2(wb, v[kx+dx], acc[1][dy][dx]);
                        }
                    }
                }
            }
            if(r<5){
                #pragma unroll
                for(int j=0;j<8;j++) v[j]=vn[j];
            }
        }
    }

    float rs0 = 1.0f/wex[0];
    float rs1 = 1.0f/wex[1];
    float bi0 = wex[2];
    float bi1 = wex[3];
    int gx = bx*TX5 + tx;
    if(gx < W){
        #pragma unroll
        for(int dy=0;dy<2;dy++){
            int gy = by*TY5 + ty + dy;
            if(gy>=H) continue;
            #pragma unroll
            for(int a=0;a<2;a++){
                float d0,n0,d1,n1,d2,n2,d3,n3;
                unpack2(acc[a][dy][0], d0, n0);
                unpack2(acc[a][dy][1], d1, n1);
                unpack2(acc[a][dy][2], d2, n2);
                unpack2(acc[a][dy][3], d3, n3);
                float bia = a ? bi1 : bi0;
                float rsa = a ? rs1 : rs0;
                float4 xo = make_float4(n0/(d0+EPSV)+bia, n1/(d1+EPSV)+bia,
                                        n2/(d2+EPSV)+bia, n3/(d3+EPSV)+bia);
                float4 co = make_float4(d0*rsa, d1*rsa, d2*rsa, d3*rsa);
                size_t o = (size_t)(b*2+a)*P + (size_t)gy*W + gx;
                *(float4*)&xout[o]  = xo;
                *(float4*)&cout_[o] = co;
            }
        }
    }
}

// ---------------- tiled 3x3 cat nconv, row-once, 4x2/thread ----------------
#define TX3 64
#define TY3 16
#define SW3 (TX3+2)   // 66
#define SH3 (TY3+2)   // 18

template<bool UP_FIRST>
__global__ void __launch_bounds__(128)
k_nconv3t(const float* __restrict__ xa, const float* __restrict__ ca,
          const float* __restrict__ xb, const float* __restrict__ cb,
          const float* __restrict__ w,  const float* __restrict__ wsum,
          const float* __restrict__ bias,
          float* __restrict__ xout, float* __restrict__ cout_,
          int H, int W, int bpr, int bpc){
    __shared__ __align__(16) float2 sm[4][SH3*SW3];
    __shared__ __align__(16) ull  wpk2[72];
    __shared__ float wex[4];

    const int t = threadIdx.x;
    const int P = H*W;
    const int Wh = W>>1, Ph = (W>>1)*(H>>1);

    for(int i=t;i<36;i+=128){
        wpk2[2*i]   = dupf(w[i]);
        wpk2[2*i+1] = dupf(w[36+i]);
    }
    if(t<2){ wex[t]=wsum[t]; wex[2+t]=bias[t]; }

    int bx = blockIdx.x % bpr;
    int tmp = blockIdx.x / bpr;
    int by = tmp % bpc;
    int b  = tmp / bpc;
    int gx0 = bx*TX3 - 1;
    int gy0 = by*TY3 - 1;

    #pragma unroll
    for(int ci=0;ci<4;ci++){
        const bool fromUp = UP_FIRST ? (ci<2) : (ci>=2);
        const int ch = fromUp ? (UP_FIRST ? ci : ci-2) : (UP_FIRST ? ci-2 : ci);
        const float* cs = fromUp ? (cb + (size_t)(b*2+ch)*Ph) : (ca + (size_t)(b*2+ch)*P);
        const float* xs = fromUp ? (xb + (size_t)(b*2+ch)*Ph) : (xa + (size_t)(b*2+ch)*P);
        for(int i=t;i<SH3*SW3;i+=128){
            int lx = i % SW3, ly = i / SW3;
            int gx = gx0+lx, gy = gy0+ly;
            float c=0.f, d=0.f;
            if((unsigned)gx<(unsigned)W && (unsigned)gy<(unsigned)H){
                int o = fromUp ? ((gy>>1)*Wh + (gx>>1)) : (gy*W+gx);
                c = cs[o]; d = xs[o]*c;
            }
            sm[ci][i] = make_float2(c, d);
        }
    }
    __syncthreads();

    const int tx = (t & 15)*4;
    const int ty = (t >> 4)*2;

    ull acc[2][2][4];
    #pragma unroll
    for(int a=0;a<2;a++)
      #pragma unroll
      for(int dy=0;dy<2;dy++)
        #pragma unroll
        for(int dx=0;dx<4;dx++) acc[a][dy][dx]=0ull;

    #pragma unroll
    for(int ci=0;ci<4;ci++){
        ull v[6];
        {
            const longlong2* p = (const longlong2*)&sm[ci][ty*SW3 + tx];
            #pragma unroll
            for(int j=0;j<3;j++){ longlong2 q=p[j]; v[2*j]=(ull)q.x; v[2*j+1]=(ull)q.y; }
        }
        #pragma unroll
        for(int r=0;r<4;r++){
            ull vn[6];
            if(r<3){
                const longlong2* p = (const longlong2*)&sm[ci][(ty+r+1)*SW3 + tx];
                #pragma unroll
                for(int j=0;j<3;j++){ longlong2 q=p[j]; vn[2*j]=(ull)q.x; vn[2*j+1]=(ull)q.y; }
            }
            #pragma unroll
            for(int dy=0;dy<2;dy++){
                int ky = r - dy;
                if(ky>=0 && ky<=2){
                    #pragma unroll
                    for(int kx=0;kx<3;kx++){
                        longlong2 wp = *(const longlong2*)&wpk2[(ci*9+ky*3+kx)*2];
                        ull wa=(ull)wp.x, wb=(ull)wp.y;
                        #pragma unroll
                        for(int dx=0;dx<4;dx++){
                            acc[0][dy][dx]=fma2(wa, v[kx+dx], acc[0][dy][dx]);
                            acc[1][dy][dx]=fma2(wb, v[kx+dx], acc[1][dy][dx]);
                        }
                    }
                }
            }
            if(r<3){
                #pragma unroll
                for(int j=0;j<6;j++) v[j]=vn[j];
            }
        }
    }

    float rs0 = 1.0f/wex[0];
    float rs1 = 1.0f/wex[1];
    float bi0 = wex[2];
    float bi1 = wex[3];
    int gx = bx*TX3 + tx;
    if(gx < W){
        #pragma unroll
        for(int dy=0;dy<2;dy++){
            int gy = by*TY3 + ty + dy;
            if(gy>=H) continue;
            #pragma unroll
            for(int a=0;a<2;a++){
                float d0,n0,d1,n1,d2,n2,d3,n3;
                unpack2(acc[a][dy][0], d0, n0);
                unpack2(acc[a][dy][1], d1, n1);
                unpack2(acc[a][dy][2], d2, n2);
                unpack2(acc[a][dy][3], d3, n3);
                float bia = a ? bi1 : bi0;
                float rsa = a ? rs1 : rs0;
                float4 xo = make_float4(n0/(d0+EPSV)+bia, n1/(d1+EPSV)+bia,
                                        n2/(d2+EPSV)+bia, n3/(d3+EPSV)+bia);
                float4 co = make_float4(d0*rsa, d1*rsa, d2*rsa, d3*rsa);
                size_t o = (size_t)(b*2+a)*P + (size_t)gy*W + gx;
                *(float4*)&xout[o]  = xo;
                *(float4*)&cout_[o] = co;
            }
        }
    }
}

// 2x2 max-pool on conf (first-max, row-major order), gather x at argmax.
__global__ void k_pool(const float* __restrict__ cin, const float* __restrict__ xin,
                       float* __restrict__ cds, float* __restrict__ xds,
                       int Hh, int Wh){
    int idx = blockIdx.x*blockDim.x + threadIdx.x;
    int total = BB*2*Hh*Wh;
    if(idx >= total) return;
    int x = idx % Wh;
    int y = (idx / Wh) % Hh;
    int pl = idx / (Hh*Wh);
    int Wi = Wh*2;
    size_t base = (size_t)pl*(Hh*2)*Wi + (size_t)(2*y)*Wi + 2*x;
    float2 ct = *(const float2*)(cin+base);
    float2 cbm= *(const float2*)(cin+base+Wi);
    float2 xt = *(const float2*)(xin+base);
    float2 xbm= *(const float2*)(xin+base+Wi);
    float best=ct.x, bx=xt.x;
    if(ct.y >best){best=ct.y; bx=xt.y;}
    if(cbm.x>best){best=cbm.x;bx=xbm.x;}
    if(cbm.y>best){best=cbm.y;bx=xbm.y;}
    cds[idx]=best*0.25f;
    xds[idx]=bx;
}

// final 1x1 nconv, float4-vectorized
__global__ void k_nconv1x1(const float* __restrict__ xin, const float* __restrict__ cin,
                           const float* __restrict__ w, const float* __restrict__ wsum,
                           const float* __restrict__ bias,
                           float* __restrict__ xout, float* __restrict__ cout_){
    int idx = blockIdx.x*blockDim.x + threadIdx.x;
    const int Q = P0/4;
    if(idx >= BB*Q) return;
    int q = idx % Q;
    int b = idx / Q;
    const float4* x0p = (const float4*)(xin + (size_t)(b*2+0)*P0) + q;
    const float4* x1p = (const float4*)(xin + (size_t)(b*2+1)*P0) + q;
    const float4* c0p = (const float4*)(cin + (size_t)(b*2+0)*P0) + q;
    const float4* c1p = (const float4*)(cin + (size_t)(b*2+1)*P0) + q;
    float4 X0=*x0p, X1=*x1p, C0=*c0p, C1=*c1p;
    float w0=w[0], w1=w[1];
    float rsum = 1.0f/wsum[0];
    float bi = bias[0];
    float4 XO, CO;
    #pragma unroll
    for(int k=0;k<4;k++){
        float c0v = ((const float*)&C0)[k];
        float c1v = ((const float*)&C1)[k];
        float den = w0*c0v + w1*c1v;
        float nom = w0*(((const float*)&X0)[k]*c0v) + w1*(((const float*)&X1)[k]*c1v);
        ((float*)&XO)[k] = nom/(den+EPSV) + bi;
        ((float*)&CO)[k] = den*rsum;
    }
    ((float4*)(xout  + (size_t)b*P0))[q] = XO;
    ((float4*)(cout_ + (size_t)b*P0))[q] = CO;
}

extern "C" void kernel_launch(void* const* d_in, const int* in_sizes, int n_in,
                              void* d_out, int out_size){
    const float* x0 = (const float*)d_in[0];
    const float* c0 = (const float*)d_in[1];
    const float* w1 = (const float*)d_in[2];  const float* b1 = (const float*)d_in[3];
    const float* w2 = (const float*)d_in[4];  const float* b2 = (const float*)d_in[5];
    const float* w3 = (const float*)d_in[6];  const float* b3 = (const float*)d_in[7];
    const float* w4 = (const float*)d_in[8];  const float* b4 = (const float*)d_in[9];
    const float* w5 = (const float*)d_in[10]; const float* b5 = (const float*)d_in[11];
    const float* w6 = (const float*)d_in[12]; const float* b6 = (const float*)d_in[13];
    const float* w7 = (const float*)d_in[14]; const float* b7 = (const float*)d_in[15];

    float* S = nullptr;  cudaGetSymbolAddress((void**)&S,  g_scratch);
    float* Wt = nullptr; cudaGetSymbolAddress((void**)&Wt, g_w);

    float *xA=S,   *cA=S+N0,   *xB=S+2*N0, *cB=S+3*N0, *x1=S+4*N0, *c1=S+5*N0;
    float *Sh = S + 6*N0;
    float *xha=Sh, *cha=Sh+N1, *xhb=Sh+2*N1, *chb=Sh+3*N1, *x2d=Sh+4*N1, *c2d=Sh+5*N1;
    float *Sq = Sh + 6*N1;
    float *xq=Sq,  *cq=Sq+N2,  *x3d=Sq+2*N2, *c3d=Sq+3*N2, *x34=Sq+4*N2, *c34=Sq+5*N2;
    float *Se = Sq + 6*N2;
    float *xe=Se,  *ce=Se+N3,  *x4=Se+2*N3,  *c4=Se+3*N3;

    const int thr = 256;
    auto gb = [&](long n){ return (int)((n + thr - 1) / thr); };
    auto tiles = [&](int H, int W, int &bpr, int &bpc)->int{
        bpr = (W + TX5 - 1)/TX5; bpc = (H + TY5 - 1)/TY5;
        return bpr*bpc*BB;
    };

    k_prep<<<1,128>>>(w1,w2,w3,w4,w5,w6,w7);

    int bpr, bpc, g;

    // encoder full res
    g = tiles(H0,W0,bpr,bpc);
    k_nconv5t<1><<<g,128>>>(x0, c0, Wt+0,   Wt+468, b1, xA, cA, H0, W0, bpr, bpc);
    k_nconv5t<2><<<g,128>>>(xA, cA, Wt+50,  Wt+470, b2, xB, cB, H0, W0, bpr, bpc);
    k_nconv5t<2><<<g,128>>>(xB, cB, Wt+150, Wt+472, b3, x1, c1, H0, W0, bpr, bpc);

    // level 1
    k_pool<<<gb((long)BB*2*P1),thr>>>(c1, x1, cha, xha, H1, W1);
    g = tiles(H1,W1,bpr,bpc);
    k_nconv5t<2><<<g,128>>>(xha, cha, Wt+50,  Wt+470, b2, xhb, chb, H1, W1, bpr, bpc);
    k_nconv5t<2><<<g,128>>>(xhb, chb, Wt+150, Wt+472, b3, x2d, c2d, H1, W1, bpr, bpc);

    // level 2
    k_pool<<<gb((long)BB*2*P2),thr>>>(c2d, x2d, cq, xq, H2, W2);
    g = tiles(H2,W2,bpr,bpc);
    k_nconv5t<2><<<g,128>>>(xq, cq, Wt+50, Wt+470, b2, x3d, c3d, H2, W2, bpr, bpc);

    // level 3
    k_pool<<<gb((long)BB*2*P3),thr>>>(c3d, x3d, ce, xe, H3, W3);
    g = tiles(H3,W3,bpr,bpc);
    k_nconv5t<2><<<g,128>>>(xe, ce, Wt+50, Wt+470, b2, x4, c4, H3, W3, bpr, bpc);

    // decoder
    g = tiles(H2,W2,bpr,bpc);
    k_nconv3t<false><<<g,128>>>(x3d, c3d, x4, c4,  Wt+250, Wt+474, b4, x34, c34, H2, W2, bpr, bpc);
    g = tiles(H1,W1,bpr,bpc);
    k_nconv3t<false><<<g,128>>>(x2d, c2d, x34, c34, Wt+322, Wt+476, b5, xha, cha, H1, W1, bpr, bpc);
    g = tiles(H0,W0,bpr,bpc);
    k_nconv3t<true><<<g,128>>>(x1, c1, xha, cha,   Wt+394, Wt+478, b6, xA, cA, H0, W0, bpr, bpc);

    float* out = (float*)d_out;
    k_nconv1x1<<<gb((long)BB*(P0/4)),thr>>>(xA, cA, Wt+466, Wt+480, b7,
                                            out, out + (size_t)BB*P0);
}